// round 3
// baseline (speedup 1.0000x reference)
#include <cuda_runtime.h>
#include <stdint.h>

// Unpool (max_unpool_with_argmax) — gather formulation.
// val:  float32 [B=16, H=64,  W=64,  C=128]
// mask: int32 or int64 [B,H,W,C] — global flat index into output [B, 2H, 2W, C]
//       (dtype detected at launch from in_sizes; JAX x64-disabled gives int32)
// out:  float32 [B, 128, 128, 128]
//
// out[o] = (mask[src(o)] == o) ? val[src(o)] : 0
// src(b,h2,w2,c) = (b, h2>>1, w2>>1, c)
//
// All dims are powers of two:
//   C = 128, W2 = H2 = 128, B = 16
//   out float4 count = 16*128*128*128/4 = 8,388,608
//   input strides (elems): b:524288, h:8192, w:128

__global__ __launch_bounds__(256)
void unpool_gather_i32(const float* __restrict__ val,
                       const int*   __restrict__ mask,
                       float* __restrict__ out)
{
    unsigned int o = blockIdx.x * blockDim.x + threadIdx.x;

    unsigned int c4 = o & 31u;
    unsigned int w2 = (o >> 5) & 127u;
    unsigned int h2 = (o >> 12) & 127u;
    unsigned int b  = o >> 19;

    unsigned int in_idx = b * 524288u + (h2 >> 1) * 8192u + (w2 >> 1) * 128u + (c4 << 2);

    float4 v = *reinterpret_cast<const float4*>(val + in_idx);
    int4   m = *reinterpret_cast<const int4*>(mask + in_idx);

    int out_flat = (int)(o << 2);

    float4 r;
    r.x = (m.x == out_flat    ) ? v.x : 0.0f;
    r.y = (m.y == out_flat + 1) ? v.y : 0.0f;
    r.z = (m.z == out_flat + 2) ? v.z : 0.0f;
    r.w = (m.w == out_flat + 3) ? v.w : 0.0f;

    *reinterpret_cast<float4*>(out + ((size_t)o << 2)) = r;
}

__global__ __launch_bounds__(256)
void unpool_gather_i64(const float* __restrict__ val,
                       const long long* __restrict__ mask,
                       float* __restrict__ out)
{
    unsigned int o = blockIdx.x * blockDim.x + threadIdx.x;

    unsigned int c4 = o & 31u;
    unsigned int w2 = (o >> 5) & 127u;
    unsigned int h2 = (o >> 12) & 127u;
    unsigned int b  = o >> 19;

    unsigned int in_idx = b * 524288u + (h2 >> 1) * 8192u + (w2 >> 1) * 128u + (c4 << 2);

    float4    v   = *reinterpret_cast<const float4*>(val + in_idx);
    longlong2 m01 = *reinterpret_cast<const longlong2*>(mask + in_idx);
    longlong2 m23 = *reinterpret_cast<const longlong2*>(mask + in_idx + 2);

    long long out_flat = (long long)o << 2;

    float4 r;
    r.x = (m01.x == out_flat    ) ? v.x : 0.0f;
    r.y = (m01.y == out_flat + 1) ? v.y : 0.0f;
    r.z = (m23.x == out_flat + 2) ? v.z : 0.0f;
    r.w = (m23.y == out_flat + 3) ? v.w : 0.0f;

    *reinterpret_cast<float4*>(out + ((size_t)o << 2)) = r;
}

extern "C" void kernel_launch(void* const* d_in, const int* in_sizes, int n_in,
                              void* d_out, int out_size)
{
    const float* val = (const float*)d_in[0];
    float*       out = (float*)d_out;

    const unsigned int n4 = 8388608u;   // 16*128*128*128 / 4
    const unsigned int threads = 256u;
    const unsigned int blocks = n4 / threads;  // 32768

    // in_sizes reports element counts. If the harness accounts the mask as
    // int64 it may report the same element count with 8-byte elements; we
    // can't see bytes here, so key off a conservative check: element counts
    // are equal for both interpretations, so default to int32 (JAX default,
    // x64 disabled). Only if the harness reports DOUBLE the element count
    // (i.e. raw 4-byte words of an int64 buffer) use the int64 path.
    if (n_in >= 2 && in_sizes[1] == 2 * in_sizes[0]) {
        unpool_gather_i64<<<blocks, threads>>>(val, (const long long*)d_in[1], out);
    } else {
        unpool_gather_i32<<<blocks, threads>>>(val, (const int*)d_in[1], out);
    }
}

// round 5
// speedup vs baseline: 1.1615x; 1.1615x over previous
#include <cuda_runtime.h>
#include <stdint.h>

// Unpool (max_unpool_with_argmax) — inverse-scatter, one thread per INPUT float4.
// val:  float32 [B=16, H=64, W=64, C=128]
// mask: int32   [B,H,W,C] — global flat index into output [B,128,128,128]
// out:  float32 [B,128,128,128]
//
// Thread i handles input float4 group i: loads val+mask ONCE, writes the 2x2
// output neighborhood (dh,dw in {0,1}) with (mask==out_idx ? val : 0).
// Warp = 32 consecutive c4 -> each of the 4 stores is a contiguous 512B row
// segment: fully coalesced. Output stores use .cg (no L1 allocate; output is
// write-once) to keep L1/L2 capacity for the read stream.
//
// Output strides (float elems): b*2097152 + h2*16384 + w2*128 + c
//   base0 = b*2097152 + h*32768 + w*256 + c4*4   (dh=0,dw=0)
//   dw=1: +128   dh=1: +16384   both: +16512

__device__ __forceinline__ void stcg4(float* p, float4 v) {
    asm volatile("st.global.cg.v4.f32 [%0], {%1,%2,%3,%4};"
                 :: "l"(p), "f"(v.x), "f"(v.y), "f"(v.z), "f"(v.w) : "memory");
}

__global__ __launch_bounds__(256)
void unpool_scatter4_i32(const float* __restrict__ val,
                         const int*   __restrict__ mask,
                         float* __restrict__ out)
{
    unsigned int i = blockIdx.x * blockDim.x + threadIdx.x;  // input float4 id

    unsigned int c4 = i & 31u;
    unsigned int w  = (i >> 5) & 63u;
    unsigned int h  = (i >> 11) & 63u;
    unsigned int b  = i >> 17;

    float4 v = *reinterpret_cast<const float4*>(val + ((size_t)i << 2));
    int4   m = *reinterpret_cast<const int4*>(mask + ((size_t)i << 2));

    unsigned int base0 = b * 2097152u + h * 32768u + w * 256u + (c4 << 2);

    int f00 = (int)base0;           // dh=0, dw=0
    int f01 = (int)base0 + 128;     // dh=0, dw=1
    int f10 = (int)base0 + 16384;   // dh=1, dw=0
    int f11 = (int)base0 + 16512;   // dh=1, dw=1

    float4 r00, r01, r10, r11;
    r00.x = (m.x == f00    ) ? v.x : 0.0f;
    r00.y = (m.y == f00 + 1) ? v.y : 0.0f;
    r00.z = (m.z == f00 + 2) ? v.z : 0.0f;
    r00.w = (m.w == f00 + 3) ? v.w : 0.0f;

    r01.x = (m.x == f01    ) ? v.x : 0.0f;
    r01.y = (m.y == f01 + 1) ? v.y : 0.0f;
    r01.z = (m.z == f01 + 2) ? v.z : 0.0f;
    r01.w = (m.w == f01 + 3) ? v.w : 0.0f;

    r10.x = (m.x == f10    ) ? v.x : 0.0f;
    r10.y = (m.y == f10 + 1) ? v.y : 0.0f;
    r10.z = (m.z == f10 + 2) ? v.z : 0.0f;
    r10.w = (m.w == f10 + 3) ? v.w : 0.0f;

    r11.x = (m.x == f11    ) ? v.x : 0.0f;
    r11.y = (m.y == f11 + 1) ? v.y : 0.0f;
    r11.z = (m.z == f11 + 2) ? v.z : 0.0f;
    r11.w = (m.w == f11 + 3) ? v.w : 0.0f;

    stcg4(out + base0,          r00);
    stcg4(out + base0 + 128u,   r01);
    stcg4(out + base0 + 16384u, r10);
    stcg4(out + base0 + 16512u, r11);
}

// int64-mask fallback (dtype robustness; same structure)
__global__ __launch_bounds__(256)
void unpool_scatter4_i64(const float* __restrict__ val,
                         const long long* __restrict__ mask,
                         float* __restrict__ out)
{
    unsigned int i = blockIdx.x * blockDim.x + threadIdx.x;

    unsigned int c4 = i & 31u;
    unsigned int w  = (i >> 5) & 63u;
    unsigned int h  = (i >> 11) & 63u;
    unsigned int b  = i >> 17;

    float4 v = *reinterpret_cast<const float4*>(val + ((size_t)i << 2));
    longlong2 m01 = *reinterpret_cast<const longlong2*>(mask + ((size_t)i << 2));
    longlong2 m23 = *reinterpret_cast<const longlong2*>(mask + ((size_t)i << 2) + 2);

    unsigned int base0 = b * 2097152u + h * 32768u + w * 256u + (c4 << 2);

    long long mm[4] = { m01.x, m01.y, m23.x, m23.y };
    float     vv[4] = { v.x, v.y, v.z, v.w };
    unsigned int off[4] = { 0u, 128u, 16384u, 16512u };

    #pragma unroll
    for (int p = 0; p < 4; p++) {
        long long f = (long long)(base0 + off[p]);
        float4 r;
        r.x = (mm[0] == f    ) ? vv[0] : 0.0f;
        r.y = (mm[1] == f + 1) ? vv[1] : 0.0f;
        r.z = (mm[2] == f + 2) ? vv[2] : 0.0f;
        r.w = (mm[3] == f + 3) ? vv[3] : 0.0f;
        stcg4(out + base0 + off[p], r);
    }
}

extern "C" void kernel_launch(void* const* d_in, const int* in_sizes, int n_in,
                              void* d_out, int out_size)
{
    const float* val = (const float*)d_in[0];
    float*       out = (float*)d_out;

    const unsigned int n4 = 2097152u;   // 16*64*64*128 / 4 input float4 groups
    const unsigned int threads = 256u;
    const unsigned int blocks = n4 / threads;  // 8192

    if (n_in >= 2 && in_sizes[1] == 2 * in_sizes[0]) {
        unpool_scatter4_i64<<<blocks, threads>>>(val, (const long long*)d_in[1], out);
    } else {
        unpool_scatter4_i32<<<blocks, threads>>>(val, (const int*)d_in[1], out);
    }
}